// round 6
// baseline (speedup 1.0000x reference)
#include <cuda_runtime.h>
#include <cuda_bf16.h>
#include <cstdint>

#define BB 32
#define NN 2048
#define DD 512
#define EE 512
#define VV 32000
#define TT 32
#define NSTEP 31
#define MM (NSTEP * BB)   // 992

typedef unsigned long long ull;

// ---------------- scratch ----------------------------------------------------
__device__ float g_h[BB * DD];
__device__ float g_Hall[MM * DD];
__device__ float g_HW[MM * DD];
__device__ float g_scores[MM * NN];         // 8.1 MB
__device__ float g_gx[MM * 4 * DD];         // 8.1 MB  (x-side gates + biases)
__device__ float g_gp[8 * BB * 4 * DD];     // 2 MB    (h-side partials, 8 k-slices)
__device__ float g_h0part[4 * BB * DD];
__device__ float g_cntpad[BB];
__device__ float g_cntptr[BB];
__device__ int   g_mask_mode;
__device__ unsigned g_flags[128];

// ---------------- helpers -----------------------------------------------------
__device__ __forceinline__ bool getmask(const void* p, int idx) {
    int m = g_mask_mode;
    if (m == 1) return ((const int*)p)[idx] != 0;
    if (m == 2) return ((const float*)p)[idx] != 0.0f;
    return ((const unsigned char*)p)[idx] != 0;
}
__device__ __forceinline__ float sigm(float x) { return 1.0f / (1.0f + expf(-x)); }

__device__ __forceinline__ ull ld2(const float* p) { return *(const ull*)p; }
__device__ __forceinline__ ull fma2(ull a, ull b, ull c) {
    ull d;
    asm("fma.rn.f32x2 %0, %1, %2, %3;" : "=l"(d) : "l"(a), "l"(b), "l"(c));
    return d;
}
__device__ __forceinline__ ull add2(ull a, ull b) {
    ull d;
    asm("add.rn.f32x2 %0, %1, %2;" : "=l"(d) : "l"(a), "l"(b));
    return d;
}
__device__ __forceinline__ float sum2(ull v) {
    return __uint_as_float((unsigned)v) + __uint_as_float((unsigned)(v >> 32));
}

// ---------------- setup kernels ----------------------------------------------
__global__ void detect_kernel(const int* pad_as_int) {
    int tid = threadIdx.x;
    if (tid < 128) g_flags[tid] = 0;
    if (tid == 0) {
        int v = pad_as_int[0];
        g_mask_mode = (v == 1) ? 1 : ((v == 0x3F800000) ? 2 : 0);
    }
}

__global__ void zero_kernel(float4* out, int n4) {
    int idx = blockIdx.x * blockDim.x + threadIdx.x;
    int stride = gridDim.x * blockDim.x;
    float4 z = {0.f, 0.f, 0.f, 0.f};
    for (int i = idx; i < n4; i += stride) out[i] = z;
}

__global__ void sos_kernel(float* out, const int* sosp) {
    int b = threadIdx.x;
    if (b < BB) out[(size_t)b * VV + sosp[0]] = 1.0f;
}

// ---------------- xgemm: gates_x[m][R] = emb[tok(m)]·W_ih[R] + b_ih + b_hh ---
// grid (32 R-tiles of 64, 16 m-tiles of 64), 256 threads, 4x4 f32x2 tile,
// double-buffered smem. SMEM stores are 8B (float2) — stride-34 rows are only
// 8B aligned, 16B stores trap.
__global__ void __launch_bounds__(256) xgemm_kernel(
        const float* __restrict__ emb, const float* __restrict__ Wih,
        const float* __restrict__ bih, const float* __restrict__ bhh,
        const int* __restrict__ target, const int* __restrict__ sosp) {
    __shared__ float Ws[2][64][34];
    __shared__ float Xs[2][64][34];
    __shared__ int toks[64];
    int tid = threadIdx.x;
    int Rbase = blockIdx.x * 64;
    int mbase = blockIdx.y * 64;
    if (tid < 64) {
        int m = mbase + tid;
        int t = m >> 5, b = m & 31;
        int tok = sosp[0];
        if (m < MM && t > 0) tok = target[t * BB + b];
        toks[tid] = tok;
    }
    __syncthreads();
    // prologue: load k-chunk 0 into buffer 0
    #pragma unroll
    for (int q = 0; q < 2; q++) {
        int i = tid + 256 * q;
        int row = i >> 3, c4 = i & 7;
        float4 w = *(const float4*)&Wih[(size_t)(Rbase + row) * 512 + c4 * 4];
        float4 x = *(const float4*)&emb[(size_t)toks[row] * 512 + c4 * 4];
        *(float2*)&Ws[0][row][c4 * 4]     = make_float2(w.x, w.y);
        *(float2*)&Ws[0][row][c4 * 4 + 2] = make_float2(w.z, w.w);
        *(float2*)&Xs[0][row][c4 * 4]     = make_float2(x.x, x.y);
        *(float2*)&Xs[0][row][c4 * 4 + 2] = make_float2(x.z, x.w);
    }
    __syncthreads();
    int rl = tid & 15, mg = tid >> 4;
    ull acc[4][4] = {};
    float4 wst[2], xst[2];
    for (int kt = 0; kt < 16; kt++) {
        int cur = kt & 1;
        if (kt < 15) {
            int k0 = (kt + 1) * 32;
            #pragma unroll
            for (int q = 0; q < 2; q++) {
                int i = tid + 256 * q;
                int row = i >> 3, c4 = i & 7;
                wst[q] = *(const float4*)&Wih[(size_t)(Rbase + row) * 512 + k0 + c4 * 4];
                xst[q] = *(const float4*)&emb[(size_t)toks[row] * 512 + k0 + c4 * 4];
            }
        }
        #pragma unroll
        for (int kp = 0; kp < 16; kp++) {
            ull wv[4], xv[4];
            #pragma unroll
            for (int i = 0; i < 4; i++) wv[i] = ld2(&Ws[cur][rl + 16 * i][kp * 2]);
            #pragma unroll
            for (int j = 0; j < 4; j++) xv[j] = ld2(&Xs[cur][mg * 4 + j][kp * 2]);
            #pragma unroll
            for (int i = 0; i < 4; i++)
                #pragma unroll
                for (int j = 0; j < 4; j++)
                    acc[i][j] = fma2(wv[i], xv[j], acc[i][j]);
        }
        if (kt < 15) {
            __syncthreads();
            int nb = cur ^ 1;
            #pragma unroll
            for (int q = 0; q < 2; q++) {
                int i = tid + 256 * q;
                int row = i >> 3, c4 = i & 7;
                *(float2*)&Ws[nb][row][c4 * 4]     = make_float2(wst[q].x, wst[q].y);
                *(float2*)&Ws[nb][row][c4 * 4 + 2] = make_float2(wst[q].z, wst[q].w);
                *(float2*)&Xs[nb][row][c4 * 4]     = make_float2(xst[q].x, xst[q].y);
                *(float2*)&Xs[nb][row][c4 * 4 + 2] = make_float2(xst[q].z, xst[q].w);
            }
            __syncthreads();
        }
    }
    #pragma unroll
    for (int j = 0; j < 4; j++) {
        int m = mbase + mg * 4 + j;
        if (m >= MM) continue;
        #pragma unroll
        for (int i = 0; i < 4; i++) {
            int R = Rbase + rl + 16 * i;
            g_gx[((size_t)m << 11) + R] = sum2(acc[i][j]) + bih[R] + bhh[R];
        }
    }
}

// ---------------- flag barrier: distinct-slot release stores, parallel poll --
__device__ __forceinline__ void flagbar(int bid, unsigned cnt) {
    __syncthreads();
    if (threadIdx.x == 0) {
        asm volatile("st.release.gpu.global.u32 [%0], %1;"
                     :: "l"(&g_flags[bid]), "r"(cnt) : "memory");
    }
    unsigned v = cnt;
    bool done;
    do {
        if (threadIdx.x < 128) {
            asm volatile("ld.acquire.gpu.global.u32 %0, [%1];"
                         : "=r"(v) : "l"(&g_flags[threadIdx.x]) : "memory");
        }
        done = (__syncthreads_count((int)(v >= cnt)) == 256);
    } while (!done);
}

// ---------------- persistent kernel: h0 + counts + LSTM recurrence -----------
// 128 blocks x 256 threads.
// Phase 0: block = (b = bid>>2, nslice = bid&3): partial h0 sums + counts.
// Recurrence: block = (dt = bid>>3, s = bid&7); thread = (kc = tid>>7, rl = tid&127).
// W_hh slice lives in registers; h broadcast from smem; per-block flag barrier.
__global__ void __launch_bounds__(256) lstm_persistent(
        const float* __restrict__ Whh, const float* __restrict__ enc,
        const void* pad, const void* ptrm) {
    __shared__ ull   hsu[2][32][16];       // 8 KB staged h slice
    __shared__ float psum[2][32][128];     // 32 KB kc-half partials
    __shared__ int   red1[256], red2[256];
    int tid = threadIdx.x;
    int bid = blockIdx.x;

    // ---- phase 0: h0 partial sums over enc + pointer counts ----
    {
        int b = bid >> 2, ns = bid & 3;
        int d0 = tid * 2;
        ull acc = 0;
        int n0 = ns * 512;
        for (int n = n0; n < n0 + 512; n++) {
            if (getmask(pad, b * NN + n))
                acc = add2(acc, ld2(&enc[((size_t)(b * NN + n) << 9) + d0]));
        }
        *(ull*)&g_h0part[((ns * BB) + b) * DD + d0] = acc;
        if (ns == 0) {
            int c1 = 0, c2 = 0;
            for (int n = tid; n < NN; n += 256) {
                c1 += getmask(pad, b * NN + n) ? 1 : 0;
                c2 += getmask(ptrm, b * NN + n) ? 1 : 0;
            }
            red1[tid] = c1; red2[tid] = c2; __syncthreads();
            for (int s = 128; s > 0; s >>= 1) {
                if (tid < s) { red1[tid] += red1[tid + s]; red2[tid] += red2[tid + s]; }
                __syncthreads();
            }
            if (tid == 0) { g_cntpad[b] = (float)red1[0]; g_cntptr[b] = (float)red2[0]; }
        }
    }
    unsigned cnt = 1;
    flagbar(bid, cnt);

    // ---- recurrence setup ----
    int dt = bid >> 3, s = bid & 7;
    int k0 = s * 64;
    int kc = tid >> 7, rl = tid & 127;
    int gg_ = rl >> 5, dl = rl & 31;
    int R = gg_ * 512 + dt * 32 + dl;

    ull W[16];
    {
        const float* wp = Whh + (size_t)R * 512 + k0 + kc * 32;
        #pragma unroll
        for (int j = 0; j < 16; j++) W[j] = ld2(wp + 2 * j);
    }

    // pointwise ownership: (pb, pd) per thread for tid < 128
    float creg = 0.f;
    int pd = 0, pb = 0;
    if (tid < 128) {
        int idx = bid * 128 + tid;
        pd = idx & 511; pb = idx >> 9;
        float ssum = 0.f;
        #pragma unroll
        for (int z = 0; z < 4; z++) ssum += g_h0part[((z * BB) + pb) * DD + pd];
        float h0 = ssum / g_cntpad[pb];
        creg = h0;
        g_h[pb * DD + pd] = h0;
    }
    cnt++; flagbar(bid, cnt);   // h0 visible to all blocks

    for (int t = 0; t < NSTEP; t++) {
        // stage h slice: hsu[kc2][b][j] = h[b][k0 + kc2*32 + 2j .. +1]
        #pragma unroll
        for (int q = 0; q < 4; q++) {
            int i = tid + q * 256;
            int j = i & 15, cb = i >> 4;
            int b2 = cb & 31, kc2 = cb >> 5;
            hsu[kc2][b2][j] = ld2(&g_h[b2 * 512 + k0 + kc2 * 32 + 2 * j]);
        }
        __syncthreads();

        // GEMM: W in regs, h broadcast from smem
        #pragma unroll 4
        for (int b = 0; b < 32; b++) {
            ull acc = 0;
            #pragma unroll
            for (int j = 0; j < 16; j++) acc = fma2(W[j], hsu[kc][b][j], acc);
            psum[kc][b][rl] = sum2(acc);
        }
        __syncthreads();

        // combine kc halves, store partials gp[s][b][R]
        #pragma unroll
        for (int q = 0; q < 16; q++) {
            int i = tid + q * 256;
            int b = i >> 7, r2 = i & 127;
            float v = psum[0][b][r2] + psum[1][b][r2];
            int Rr = (r2 >> 5) * 512 + dt * 32 + (r2 & 31);
            g_gp[((s * BB + b) << 11) + Rr] = v;
        }
        cnt++; flagbar(bid, cnt);    // partials ready

        if (tid < 128) {
            const float* gx = g_gx + ((size_t)(t * BB + pb) << 11);
            float gi = gx[pd], gf = gx[512 + pd], gg = gx[1024 + pd], go = gx[1536 + pd];
            #pragma unroll
            for (int ss = 0; ss < 8; ss++) {
                const float* gp = g_gp + ((size_t)(ss * BB + pb) << 11);
                gi += gp[pd]; gf += gp[512 + pd]; gg += gp[1024 + pd]; go += gp[1536 + pd];
            }
            float cn = sigm(gf) * creg + sigm(gi) * tanhf(gg);
            float hn = sigm(go) * tanhf(cn);
            creg = cn;
            g_h[pb * 512 + pd] = hn;
            g_Hall[((size_t)(t * BB + pb) << 9) + pd] = hn;
        }
        cnt++; flagbar(bid, cnt);    // h ready
    }
}

// ---------------- hw: HW[m][n] = Hall[m]·W_att[n] ----------------------------
__global__ void __launch_bounds__(256) hw_kernel(const float* __restrict__ Watt) {
    __shared__ float As[64][66];
    __shared__ float Ws[64][66];
    int tid = threadIdx.x;
    int mbase = blockIdx.x * 64;
    int nbase = blockIdx.y * 64;
    int tx = tid & 15;
    int ty = tid >> 4;
    ull acc[4][4] = {};
    for (int k0 = 0; k0 < 512; k0 += 32) {
        __syncthreads();
        #pragma unroll
        for (int i = 0; i < 8; i++) {
            int lin = tid + 256 * i;
            int row = lin >> 5, c = lin & 31;
            int m = mbase + row;
            As[row][c] = (m < MM) ? g_Hall[((size_t)m << 9) + k0 + c] : 0.f;
            Ws[row][c] = Watt[(size_t)(nbase + row) * 512 + k0 + c];
        }
        __syncthreads();
        #pragma unroll
        for (int kp = 0; kp < 16; kp++) {
            ull av[4], wv[4];
            #pragma unroll
            for (int j = 0; j < 4; j++) av[j] = ld2(&As[ty * 4 + j][kp * 2]);
            #pragma unroll
            for (int i = 0; i < 4; i++) wv[i] = ld2(&Ws[tx + 16 * i][kp * 2]);
            #pragma unroll
            for (int i = 0; i < 4; i++)
                #pragma unroll
                for (int j = 0; j < 4; j++)
                    acc[i][j] = fma2(av[j], wv[i], acc[i][j]);
        }
    }
    #pragma unroll
    for (int j = 0; j < 4; j++) {
        int m = mbase + ty * 4 + j;
        if (m >= MM) continue;
        #pragma unroll
        for (int i = 0; i < 4; i++)
            g_HW[((size_t)m << 9) + nbase + tx + 16 * i] = sum2(acc[i][j]);
    }
}

// ---------------- scores[t][b][n] = enc[b][n]·HW[t*B+b] ----------------------
__global__ void __launch_bounds__(256) scores_kernel(const float* __restrict__ enc) {
    __shared__ float Es[256][34];
    __shared__ float Hs[32][34];
    int tid = threadIdx.x;
    int nbase = blockIdx.x << 8;
    int b = blockIdx.y;
    int nl = tid & 31;
    int tg = tid >> 5;
    ull acc[8][4] = {};
    for (int k0 = 0; k0 < 512; k0 += 32) {
        __syncthreads();
        #pragma unroll
        for (int i = 0; i < 32; i++) {
            int lin = tid + 256 * i;
            int row = lin >> 5, c = lin & 31;
            Es[row][c] = enc[((size_t)(b * NN + nbase + row) << 9) + k0 + c];
        }
        #pragma unroll
        for (int i = 0; i < 4; i++) {
            int lin = tid + 256 * i;
            int row = lin >> 5, c = lin & 31;
            Hs[row][c] = (row < NSTEP) ? g_HW[((size_t)(row * BB + b) << 9) + k0 + c] : 0.f;
        }
        __syncthreads();
        #pragma unroll
        for (int kp = 0; kp < 16; kp++) {
            ull ev[8], hv[4];
            #pragma unroll
            for (int i = 0; i < 8; i++) ev[i] = ld2(&Es[nl + 32 * i][kp * 2]);
            #pragma unroll
            for (int j = 0; j < 4; j++) hv[j] = ld2(&Hs[tg * 4 + j][kp * 2]);
            #pragma unroll
            for (int i = 0; i < 8; i++)
                #pragma unroll
                for (int j = 0; j < 4; j++)
                    acc[i][j] = fma2(ev[i], hv[j], acc[i][j]);
        }
    }
    #pragma unroll
    for (int j = 0; j < 4; j++) {
        int t = tg * 4 + j;
        if (t >= NSTEP) continue;
        #pragma unroll
        for (int i = 0; i < 8; i++)
            g_scores[((size_t)(t * BB + b) << 11) + nbase + nl + 32 * i] = sum2(acc[i][j]);
    }
}

// ---------------- softmax + threshold + scatter + eos ------------------------
__global__ void softmax_scatter_kernel(const void* ptrmask,
                                       const int* __restrict__ token_ids,
                                       const int* __restrict__ eosp,
                                       float* __restrict__ out) {
    int t = blockIdx.x, b = blockIdx.y, tid = threadIdx.x;
    __shared__ float sp[NN];
    __shared__ float red[256];
    const float* sc = g_scores + ((size_t)(t * BB) + b) * NN;

    float m = -1e30f;
    for (int n = tid; n < NN; n += 256) {
        bool pm = getmask(ptrmask, b * NN + n);
        float s = pm ? sc[n] : -1e30f;
        sp[n] = s;
        m = fmaxf(m, s);
    }
    red[tid] = m; __syncthreads();
    for (int s = 128; s > 0; s >>= 1) {
        if (tid < s) red[tid] = fmaxf(red[tid], red[tid + s]);
        __syncthreads();
    }
    m = red[0]; __syncthreads();

    float lsum = 0.f;
    for (int n = tid; n < NN; n += 256) {
        float s = sp[n];
        float e = (s > -1e29f) ? expf(s - m) : 0.f;
        sp[n] = e;
        lsum += e;
    }
    red[tid] = lsum; __syncthreads();
    for (int s = 128; s > 0; s >>= 1) {
        if (tid < s) red[tid] += red[tid + s];
        __syncthreads();
    }
    float sum = red[0];
    float thr = 1.0f / g_cntptr[b];
    float* orow = out + ((size_t)(t + 1)) * BB * VV + (size_t)b * VV;
    __syncthreads();

    float ks = 0.f;
    for (int n = tid; n < NN; n += 256) {
        float e = sp[n];
        if (e > 0.f) {
            float p = e / sum;
            if (p >= thr) {
                atomicAdd(&orow[token_ids[b * NN + n]], p);
                ks += p;
            }
        }
    }
    red[tid] = ks; __syncthreads();
    for (int s = 128; s > 0; s >>= 1) {
        if (tid < s) red[tid] += red[tid + s];
        __syncthreads();
    }
    if (tid == 0) {
        __threadfence();
        orow[eosp[0]] = 1.0f - red[0];
    }
}

// ---------------- host launcher ----------------------------------------------
extern "C" void kernel_launch(void* const* d_in, const int* in_sizes, int n_in,
                              void* d_out, int out_size) {
    const float* enc    = (const float*)d_in[0];
    const float* emb    = (const float*)d_in[1];
    const float* W_ih   = (const float*)d_in[2];
    const float* W_hh   = (const float*)d_in[3];
    const float* b_ih   = (const float*)d_in[4];
    const float* b_hh   = (const float*)d_in[5];
    const float* W_att  = (const float*)d_in[6];
    const void*  pad    = d_in[7];
    const void*  ptr    = d_in[8];
    const int*   tokid  = (const int*)d_in[9];
    const int*   target = (const int*)d_in[10];
    const int*   sosp   = (const int*)d_in[11];
    const int*   eosp   = (const int*)d_in[12];
    float* out = (float*)d_out;

    detect_kernel<<<1, 128>>>((const int*)pad);

    int n4 = (TT * BB * VV) / 4;
    zero_kernel<<<4096, 256>>>((float4*)out, n4);
    sos_kernel<<<1, 32>>>(out, sosp);

    {
        dim3 g(32, 16);
        xgemm_kernel<<<g, 256>>>(emb, W_ih, b_ih, b_hh, target, sosp);
    }

    lstm_persistent<<<128, 256>>>(W_hh, enc, pad, ptr);

    {
        dim3 g(16, 8);
        hw_kernel<<<g, 256>>>(W_att);
    }
    {
        dim3 g(8, BB);
        scores_kernel<<<g, 256>>>(enc);
    }
    {
        dim3 g(NSTEP, BB);
        softmax_scatter_kernel<<<g, 256>>>(ptr, tokid, eosp, out);
    }
}

// round 7
// speedup vs baseline: 1.0630x; 1.0630x over previous
#include <cuda_runtime.h>
#include <cuda_bf16.h>
#include <cstdint>

#define BB 32
#define NN 2048
#define DD 512
#define EE 512
#define VV 32000
#define TT 32
#define NSTEP 31
#define MM (NSTEP * BB)   // 992

typedef unsigned long long ull;

// ---------------- scratch ----------------------------------------------------
__device__ ulonglong2 g_hq[2][128][32];     // h packed: [parity][k/4][b], ull2 = 4 k's
__device__ float g_Hall[MM * DD];
__device__ float g_HW[MM * DD];
__device__ float g_scores[MM * NN];         // 8.1 MB
__device__ float g_gx[MM * 4 * DD];         // 8.1 MB  (x-side gates + biases)
__device__ float g_h0part[4 * BB * DD];
__device__ float g_cntpad[BB];
__device__ float g_cntptr[BB];
__device__ int   g_mask_mode;
__device__ int   g_flagsp[128][32];         // one flag per 128B line

// ---------------- helpers -----------------------------------------------------
__device__ __forceinline__ bool getmask(const void* p, int idx) {
    int m = g_mask_mode;
    if (m == 1) return ((const int*)p)[idx] != 0;
    if (m == 2) return ((const float*)p)[idx] != 0.0f;
    return ((const unsigned char*)p)[idx] != 0;
}
__device__ __forceinline__ float sigm(float x) { return 1.0f / (1.0f + expf(-x)); }

__device__ __forceinline__ ull ld2(const float* p) { return *(const ull*)p; }
__device__ __forceinline__ ull fma2(ull a, ull b, ull c) {
    ull d;
    asm("fma.rn.f32x2 %0, %1, %2, %3;" : "=l"(d) : "l"(a), "l"(b), "l"(c));
    return d;
}
__device__ __forceinline__ ull add2(ull a, ull b) {
    ull d;
    asm("add.rn.f32x2 %0, %1, %2;" : "=l"(d) : "l"(a), "l"(b));
    return d;
}
__device__ __forceinline__ float sum2(ull v) {
    return __uint_as_float((unsigned)v) + __uint_as_float((unsigned)(v >> 32));
}
__device__ __forceinline__ ull pack2(float lo, float hi) {
    return (ull)__float_as_uint(lo) | ((ull)__float_as_uint(hi) << 32);
}

// ---------------- setup kernels ----------------------------------------------
__global__ void detect_kernel(const int* pad_as_int) {
    int tid = threadIdx.x;
    if (tid < 128) g_flagsp[tid][0] = 0;
    if (tid == 0) {
        int v = pad_as_int[0];
        g_mask_mode = (v == 1) ? 1 : ((v == 0x3F800000) ? 2 : 0);
    }
}

__global__ void zero_kernel(float4* out, int n4) {
    int idx = blockIdx.x * blockDim.x + threadIdx.x;
    int stride = gridDim.x * blockDim.x;
    float4 z = {0.f, 0.f, 0.f, 0.f};
    for (int i = idx; i < n4; i += stride) out[i] = z;
}

__global__ void sos_kernel(float* out, const int* sosp) {
    int b = threadIdx.x;
    if (b < BB) out[(size_t)b * VV + sosp[0]] = 1.0f;
}

// ---------------- xgemm: gates_x[m][R] = emb[tok(m)]·W_ih[R] + b_ih + b_hh ---
__global__ void __launch_bounds__(256) xgemm_kernel(
        const float* __restrict__ emb, const float* __restrict__ Wih,
        const float* __restrict__ bih, const float* __restrict__ bhh,
        const int* __restrict__ target, const int* __restrict__ sosp) {
    __shared__ float Ws[2][64][34];
    __shared__ float Xs[2][64][34];
    __shared__ int toks[64];
    int tid = threadIdx.x;
    int Rbase = blockIdx.x * 64;
    int mbase = blockIdx.y * 64;
    if (tid < 64) {
        int m = mbase + tid;
        int t = m >> 5, b = m & 31;
        int tok = sosp[0];
        if (m < MM && t > 0) tok = target[t * BB + b];
        toks[tid] = tok;
    }
    __syncthreads();
    #pragma unroll
    for (int q = 0; q < 2; q++) {
        int i = tid + 256 * q;
        int row = i >> 3, c4 = i & 7;
        float4 w = *(const float4*)&Wih[(size_t)(Rbase + row) * 512 + c4 * 4];
        float4 x = *(const float4*)&emb[(size_t)toks[row] * 512 + c4 * 4];
        *(float2*)&Ws[0][row][c4 * 4]     = make_float2(w.x, w.y);
        *(float2*)&Ws[0][row][c4 * 4 + 2] = make_float2(w.z, w.w);
        *(float2*)&Xs[0][row][c4 * 4]     = make_float2(x.x, x.y);
        *(float2*)&Xs[0][row][c4 * 4 + 2] = make_float2(x.z, x.w);
    }
    __syncthreads();
    int rl = tid & 15, mg = tid >> 4;
    ull acc[4][4] = {};
    float4 wst[2], xst[2];
    for (int kt = 0; kt < 16; kt++) {
        int cur = kt & 1;
        if (kt < 15) {
            int k0 = (kt + 1) * 32;
            #pragma unroll
            for (int q = 0; q < 2; q++) {
                int i = tid + 256 * q;
                int row = i >> 3, c4 = i & 7;
                wst[q] = *(const float4*)&Wih[(size_t)(Rbase + row) * 512 + k0 + c4 * 4];
                xst[q] = *(const float4*)&emb[(size_t)toks[row] * 512 + k0 + c4 * 4];
            }
        }
        #pragma unroll
        for (int kp = 0; kp < 16; kp++) {
            ull wv[4], xv[4];
            #pragma unroll
            for (int i = 0; i < 4; i++) wv[i] = ld2(&Ws[cur][rl + 16 * i][kp * 2]);
            #pragma unroll
            for (int j = 0; j < 4; j++) xv[j] = ld2(&Xs[cur][mg * 4 + j][kp * 2]);
            #pragma unroll
            for (int i = 0; i < 4; i++)
                #pragma unroll
                for (int j = 0; j < 4; j++)
                    acc[i][j] = fma2(wv[i], xv[j], acc[i][j]);
        }
        if (kt < 15) {
            __syncthreads();
            int nb = cur ^ 1;
            #pragma unroll
            for (int q = 0; q < 2; q++) {
                int i = tid + 256 * q;
                int row = i >> 3, c4 = i & 7;
                *(float2*)&Ws[nb][row][c4 * 4]     = make_float2(wst[q].x, wst[q].y);
                *(float2*)&Ws[nb][row][c4 * 4 + 2] = make_float2(wst[q].z, wst[q].w);
                *(float2*)&Xs[nb][row][c4 * 4]     = make_float2(xst[q].x, xst[q].y);
                *(float2*)&Xs[nb][row][c4 * 4 + 2] = make_float2(xst[q].z, xst[q].w);
            }
            __syncthreads();
        }
    }
    #pragma unroll
    for (int j = 0; j < 4; j++) {
        int m = mbase + mg * 4 + j;
        if (m >= MM) continue;
        #pragma unroll
        for (int i = 0; i < 4; i++) {
            int R = Rbase + rl + 16 * i;
            g_gx[((size_t)m << 11) + R] = sum2(acc[i][j]) + bih[R] + bhh[R];
        }
    }
}

// ---------------- flag barrier: padded slots, release store, acquire poll ----
__device__ __forceinline__ void flagbar(int bid, unsigned cnt) {
    __syncthreads();
    if (threadIdx.x == 0) {
        asm volatile("st.release.gpu.global.u32 [%0], %1;"
                     :: "l"(&g_flagsp[bid][0]), "r"(cnt) : "memory");
    }
    unsigned v = cnt;
    bool done;
    do {
        if (threadIdx.x < 128) {
            asm volatile("ld.acquire.gpu.global.u32 %0, [%1];"
                         : "=r"(v) : "l"(&g_flagsp[threadIdx.x][0]) : "memory");
        }
        done = (__syncthreads_count((int)(v >= cnt)) == 256);
        if (!done) __nanosleep(64);
    } while (!done);
}

// ---------------- persistent kernel: h0 + counts + LSTM recurrence -----------
// 128 blocks x 256 threads. Block j owns output columns d in {4j..4j+3}:
// its 16 gate rows are R = g*512 + 4j + c. Warps split k 8 ways; partial
// combine is block-local in smem; pointwise is local (c in registers).
// ONE global barrier per step. h travels as ulonglong2 hq[k/4][b], read .cg.
__global__ void __launch_bounds__(256) lstm_persistent(
        const float* __restrict__ Whh, const float* __restrict__ enc,
        const void* pad, const void* ptrm) {
    __shared__ ulonglong2 Wq_s[16][128];   // 32 KB: W rows packed over k
    __shared__ float psum[8][16][32];      // 16 KB: per-warp k-slice partials
    __shared__ float hex[4][32];
    __shared__ int red1[256], red2[256];
    int tid = threadIdx.x;
    int bid = blockIdx.x;
    int lane = tid & 31, w = tid >> 5;
    int j = bid;

    // ---- phase 0: h0 partial sums over enc + pointer counts ----
    {
        int b = bid >> 2, ns = bid & 3;
        int d0 = tid * 2;
        int base = b * NN + ns * 512;
        ull a0 = 0, a1 = 0, a2 = 0, a3 = 0;
        for (int n = 0; n < 512; n += 4) {
            int i0 = base + n;
            if (getmask(pad, i0))     a0 = add2(a0, ld2(&enc[(size_t)(i0) * DD + d0]));
            if (getmask(pad, i0 + 1)) a1 = add2(a1, ld2(&enc[(size_t)(i0 + 1) * DD + d0]));
            if (getmask(pad, i0 + 2)) a2 = add2(a2, ld2(&enc[(size_t)(i0 + 2) * DD + d0]));
            if (getmask(pad, i0 + 3)) a3 = add2(a3, ld2(&enc[(size_t)(i0 + 3) * DD + d0]));
        }
        *(ull*)&g_h0part[(ns * BB + b) * DD + d0] = add2(add2(a0, a1), add2(a2, a3));
        if (ns == 0) {
            int c1 = 0, c2 = 0;
            for (int n = tid; n < NN; n += 256) {
                c1 += getmask(pad, b * NN + n) ? 1 : 0;
                c2 += getmask(ptrm, b * NN + n) ? 1 : 0;
            }
            red1[tid] = c1; red2[tid] = c2; __syncthreads();
            for (int s = 128; s > 0; s >>= 1) {
                if (tid < s) { red1[tid] += red1[tid + s]; red2[tid] += red2[tid + s]; }
                __syncthreads();
            }
            if (tid == 0) { g_cntpad[b] = (float)red1[0]; g_cntptr[b] = (float)red2[0]; }
        }
    }
    unsigned cnt = 1;
    flagbar(bid, cnt);

    // ---- load W_hh rows for this block's 16 gate rows (once) ----
    for (int idx = tid; idx < 16 * 128; idx += 256) {
        int r = idx >> 7, q = idx & 127;
        int g = r >> 2, c = r & 3;
        int R = g * 512 + 4 * j + c;
        Wq_s[r][q] = ((const ulonglong2*)(Whh + (size_t)R * 512))[q];
    }

    // ---- h0 finalize for owned columns; creg init ----
    float creg = 0.f;
    if (tid < 128) {
        int c = tid >> 5, b = tid & 31;
        int d = 4 * j + c;
        float ssum = 0.f;
        #pragma unroll
        for (int z = 0; z < 4; z++) ssum += g_h0part[(z * BB + b) * DD + d];
        float h0 = ssum / g_cntpad[b];
        creg = h0;
        hex[c][b] = h0;
    }
    __syncthreads();
    if (tid < 32) {
        ulonglong2 u;
        u.x = pack2(hex[0][tid], hex[1][tid]);
        u.y = pack2(hex[2][tid], hex[3][tid]);
        g_hq[0][j][tid] = u;
    }
    cnt++; flagbar(bid, cnt);

    // ---- recurrence ----
    for (int t = 0; t < NSTEP; t++) {
        const longlong2* hq = (const longlong2*)&g_hq[t & 1][0][0];
        // GEMM: warp w covers k-slice [w*64, w*64+64) = q in [w*16, w*16+16)
        ull acc[16] = {};
        #pragma unroll 4
        for (int qq = 0; qq < 16; qq++) {
            int q = w * 16 + qq;
            longlong2 hvl = __ldcg(&hq[q * 32 + lane]);   // L2-only: fresh data
            ull hx = (ull)hvl.x, hy = (ull)hvl.y;
            #pragma unroll
            for (int r = 0; r < 16; r++) {
                ulonglong2 wv = Wq_s[r][q];
                acc[r] = fma2(hx, wv.x, acc[r]);
                acc[r] = fma2(hy, wv.y, acc[r]);
            }
        }
        #pragma unroll
        for (int r = 0; r < 16; r++) psum[w][r][lane] = sum2(acc[r]);
        __syncthreads();

        if (tid < 128) {
            int c = tid >> 5, b = tid & 31;
            const float* gx = g_gx + ((size_t)(t * BB + b) << 11) + 4 * j + c;
            float gi = gx[0], gf = gx[512], gg = gx[1024], go = gx[1536];
            #pragma unroll
            for (int w2 = 0; w2 < 8; w2++) {
                gi += psum[w2][c][b];
                gf += psum[w2][4 + c][b];
                gg += psum[w2][8 + c][b];
                go += psum[w2][12 + c][b];
            }
            float cn = sigm(gf) * creg + sigm(gi) * tanhf(gg);
            float hn = sigm(go) * tanhf(cn);
            creg = cn;
            hex[c][b] = hn;
            g_Hall[(size_t)(t * BB + b) * DD + 4 * j + c] = hn;
        }
        __syncthreads();
        if (tid < 32) {
            ulonglong2 u;
            u.x = pack2(hex[0][tid], hex[1][tid]);
            u.y = pack2(hex[2][tid], hex[3][tid]);
            g_hq[(t + 1) & 1][j][tid] = u;
        }
        cnt++; flagbar(bid, cnt);
    }
}

// ---------------- hw: HW[m][n] = Hall[m]·W_att[n] ----------------------------
__global__ void __launch_bounds__(256) hw_kernel(const float* __restrict__ Watt) {
    __shared__ float As[64][66];
    __shared__ float Ws[64][66];
    int tid = threadIdx.x;
    int mbase = blockIdx.x * 64;
    int nbase = blockIdx.y * 64;
    int tx = tid & 15;
    int ty = tid >> 4;
    ull acc[4][4] = {};
    for (int k0 = 0; k0 < 512; k0 += 32) {
        __syncthreads();
        #pragma unroll
        for (int i = 0; i < 8; i++) {
            int lin = tid + 256 * i;
            int row = lin >> 5, c = lin & 31;
            int m = mbase + row;
            As[row][c] = (m < MM) ? g_Hall[((size_t)m << 9) + k0 + c] : 0.f;
            Ws[row][c] = Watt[(size_t)(nbase + row) * 512 + k0 + c];
        }
        __syncthreads();
        #pragma unroll
        for (int kp = 0; kp < 16; kp++) {
            ull av[4], wv[4];
            #pragma unroll
            for (int jj = 0; jj < 4; jj++) av[jj] = ld2(&As[ty * 4 + jj][kp * 2]);
            #pragma unroll
            for (int i = 0; i < 4; i++) wv[i] = ld2(&Ws[tx + 16 * i][kp * 2]);
            #pragma unroll
            for (int i = 0; i < 4; i++)
                #pragma unroll
                for (int jj = 0; jj < 4; jj++)
                    acc[i][jj] = fma2(av[jj], wv[i], acc[i][jj]);
        }
    }
    #pragma unroll
    for (int jj = 0; jj < 4; jj++) {
        int m = mbase + ty * 4 + jj;
        if (m >= MM) continue;
        #pragma unroll
        for (int i = 0; i < 4; i++)
            g_HW[((size_t)m << 9) + nbase + tx + 16 * i] = sum2(acc[i][jj]);
    }
}

// ---------------- scores[t][b][n] = enc[b][n]·HW[t*B+b] ----------------------
__global__ void __launch_bounds__(256) scores_kernel(const float* __restrict__ enc) {
    __shared__ float Es[256][34];
    __shared__ float Hs[32][34];
    int tid = threadIdx.x;
    int nbase = blockIdx.x << 8;
    int b = blockIdx.y;
    int nl = tid & 31;
    int tg = tid >> 5;
    ull acc[8][4] = {};
    for (int k0 = 0; k0 < 512; k0 += 32) {
        __syncthreads();
        #pragma unroll
        for (int i = 0; i < 32; i++) {
            int lin = tid + 256 * i;
            int row = lin >> 5, c = lin & 31;
            Es[row][c] = enc[((size_t)(b * NN + nbase + row) << 9) + k0 + c];
        }
        #pragma unroll
        for (int i = 0; i < 4; i++) {
            int lin = tid + 256 * i;
            int row = lin >> 5, c = lin & 31;
            Hs[row][c] = (row < NSTEP) ? g_HW[((size_t)(row * BB + b) << 9) + k0 + c] : 0.f;
        }
        __syncthreads();
        #pragma unroll
        for (int kp = 0; kp < 16; kp++) {
            ull ev[8], hv[4];
            #pragma unroll
            for (int i = 0; i < 8; i++) ev[i] = ld2(&Es[nl + 32 * i][kp * 2]);
            #pragma unroll
            for (int jj = 0; jj < 4; jj++) hv[jj] = ld2(&Hs[tg * 4 + jj][kp * 2]);
            #pragma unroll
            for (int i = 0; i < 8; i++)
                #pragma unroll
                for (int jj = 0; jj < 4; jj++)
                    acc[i][jj] = fma2(ev[i], hv[jj], acc[i][jj]);
        }
    }
    #pragma unroll
    for (int jj = 0; jj < 4; jj++) {
        int t = tg * 4 + jj;
        if (t >= NSTEP) continue;
        #pragma unroll
        for (int i = 0; i < 8; i++)
            g_scores[((size_t)(t * BB + b) << 11) + nbase + nl + 32 * i] = sum2(acc[i][jj]);
    }
}

// ---------------- softmax + threshold + scatter + eos ------------------------
__global__ void softmax_scatter_kernel(const void* ptrmask,
                                       const int* __restrict__ token_ids,
                                       const int* __restrict__ eosp,
                                       float* __restrict__ out) {
    int t = blockIdx.x, b = blockIdx.y, tid = threadIdx.x;
    __shared__ float sp[NN];
    __shared__ float red[256];
    const float* sc = g_scores + ((size_t)(t * BB) + b) * NN;

    float m = -1e30f;
    for (int n = tid; n < NN; n += 256) {
        bool pm = getmask(ptrmask, b * NN + n);
        float s = pm ? sc[n] : -1e30f;
        sp[n] = s;
        m = fmaxf(m, s);
    }
    red[tid] = m; __syncthreads();
    for (int s = 128; s > 0; s >>= 1) {
        if (tid < s) red[tid] = fmaxf(red[tid], red[tid + s]);
        __syncthreads();
    }
    m = red[0]; __syncthreads();

    float lsum = 0.f;
    for (int n = tid; n < NN; n += 256) {
        float s = sp[n];
        float e = (s > -1e29f) ? expf(s - m) : 0.f;
        sp[n] = e;
        lsum += e;
    }
    red[tid] = lsum; __syncthreads();
    for (int s = 128; s > 0; s >>= 1) {
        if (tid < s) red[tid] += red[tid + s];
        __syncthreads();
    }
    float sum = red[0];
    float thr = 1.0f / g_cntptr[b];
    float* orow = out + ((size_t)(t + 1)) * BB * VV + (size_t)b * VV;
    __syncthreads();

    float ks = 0.f;
    for (int n = tid; n < NN; n += 256) {
        float e = sp[n];
        if (e > 0.f) {
            float p = e / sum;
            if (p >= thr) {
                atomicAdd(&orow[token_ids[b * NN + n]], p);
                ks += p;
            }
        }
    }
    red[tid] = ks; __syncthreads();
    for (int s = 128; s > 0; s >>= 1) {
        if (tid < s) red[tid] += red[tid + s];
        __syncthreads();
    }
    if (tid == 0) {
        __threadfence();
        orow[eosp[0]] = 1.0f - red[0];
    }
}

// ---------------- host launcher ----------------------------------------------
extern "C" void kernel_launch(void* const* d_in, const int* in_sizes, int n_in,
                              void* d_out, int out_size) {
    const float* enc    = (const float*)d_in[0];
    const float* emb    = (const float*)d_in[1];
    const float* W_ih   = (const float*)d_in[2];
    const float* W_hh   = (const float*)d_in[3];
    const float* b_ih   = (const float*)d_in[4];
    const float* b_hh   = (const float*)d_in[5];
    const float* W_att  = (const float*)d_in[6];
    const void*  pad    = d_in[7];
    const void*  ptr    = d_in[8];
    const int*   tokid  = (const int*)d_in[9];
    const int*   target = (const int*)d_in[10];
    const int*   sosp   = (const int*)d_in[11];
    const int*   eosp   = (const int*)d_in[12];
    float* out = (float*)d_out;

    detect_kernel<<<1, 128>>>((const int*)pad);

    int n4 = (TT * BB * VV) / 4;
    zero_kernel<<<4096, 256>>>((float4*)out, n4);
    sos_kernel<<<1, 32>>>(out, sosp);

    {
        dim3 g(32, 16);
        xgemm_kernel<<<g, 256>>>(emb, W_ih, b_ih, b_hh, target, sosp);
    }

    lstm_persistent<<<128, 256>>>(W_hh, enc, pad, ptr);

    {
        dim3 g(16, 8);
        hw_kernel<<<g, 256>>>(W_att);
    }
    {
        dim3 g(8, BB);
        scores_kernel<<<g, 256>>>(enc);
    }
    {
        dim3 g(NSTEP, BB);
        softmax_scatter_kernel<<<g, 256>>>(ptr, tokid, eosp, out);
    }
}

// round 8
// speedup vs baseline: 1.1555x; 1.0870x over previous
#include <cuda_runtime.h>
#include <cuda_bf16.h>
#include <cstdint>

#define BB 32
#define NN 2048
#define DD 512
#define EE 512
#define VV 32000
#define TT 32
#define NSTEP 31
#define MM (NSTEP * BB)   // 992

typedef unsigned long long ull;

// ---------------- scratch ----------------------------------------------------
__device__ ulonglong2 g_hq[2][128][32];     // h packed: [parity][k/4][b]
__device__ float g_Hall[MM * DD];
__device__ float g_HW[MM * DD];
__device__ float g_scores[MM * NN];         // 8.1 MB
__device__ float g_gx[MM * 4 * DD];         // 8.1 MB  (x-side gates + biases)
__device__ float g_h0part[4 * BB * DD];
__device__ float g_cntpad[BB];
__device__ float g_cntptr[BB];
__device__ int   g_mask_mode;
__device__ unsigned g_arrive;

// ---------------- helpers -----------------------------------------------------
__device__ __forceinline__ bool getmask(const void* p, int idx) {
    int m = g_mask_mode;
    if (m == 1) return ((const int*)p)[idx] != 0;
    if (m == 2) return ((const float*)p)[idx] != 0.0f;
    return ((const unsigned char*)p)[idx] != 0;
}
__device__ __forceinline__ float sigm(float x) { return 1.0f / (1.0f + expf(-x)); }

__device__ __forceinline__ ull ld2(const float* p) { return *(const ull*)p; }
__device__ __forceinline__ ull fma2(ull a, ull b, ull c) {
    ull d;
    asm("fma.rn.f32x2 %0, %1, %2, %3;" : "=l"(d) : "l"(a), "l"(b), "l"(c));
    return d;
}
__device__ __forceinline__ ull add2(ull a, ull b) {
    ull d;
    asm("add.rn.f32x2 %0, %1, %2;" : "=l"(d) : "l"(a), "l"(b));
    return d;
}
__device__ __forceinline__ float sum2(ull v) {
    return __uint_as_float((unsigned)v) + __uint_as_float((unsigned)(v >> 32));
}
__device__ __forceinline__ ull pack2(float lo, float hi) {
    return (ull)__float_as_uint(lo) | ((ull)__float_as_uint(hi) << 32);
}

// ---------------- setup kernels ----------------------------------------------
__global__ void detect_kernel(const int* pad_as_int) {
    if (threadIdx.x == 0) {
        int v = pad_as_int[0];
        g_mask_mode = (v == 1) ? 1 : ((v == 0x3F800000) ? 2 : 0);
        g_arrive = 0;
    }
}

__global__ void zero_kernel(float4* out, int n4) {
    int idx = blockIdx.x * blockDim.x + threadIdx.x;
    int stride = gridDim.x * blockDim.x;
    float4 z = {0.f, 0.f, 0.f, 0.f};
    for (int i = idx; i < n4; i += stride) out[i] = z;
}

__global__ void sos_kernel(float* out, const int* sosp) {
    int b = threadIdx.x;
    if (b < BB) out[(size_t)b * VV + sosp[0]] = 1.0f;
}

// ---------------- xgemm: gates_x[m][R] = emb[tok(m)]·W_ih[R] + b_ih + b_hh ---
__global__ void __launch_bounds__(256) xgemm_kernel(
        const float* __restrict__ emb, const float* __restrict__ Wih,
        const float* __restrict__ bih, const float* __restrict__ bhh,
        const int* __restrict__ target, const int* __restrict__ sosp) {
    __shared__ float Ws[2][64][34];
    __shared__ float Xs[2][64][34];
    __shared__ int toks[64];
    int tid = threadIdx.x;
    int Rbase = blockIdx.x * 64;
    int mbase = blockIdx.y * 64;
    if (tid < 64) {
        int m = mbase + tid;
        int t = m >> 5, b = m & 31;
        int tok = sosp[0];
        if (m < MM && t > 0) tok = target[t * BB + b];
        toks[tid] = tok;
    }
    __syncthreads();
    #pragma unroll
    for (int q = 0; q < 2; q++) {
        int i = tid + 256 * q;
        int row = i >> 3, c4 = i & 7;
        float4 w = *(const float4*)&Wih[(size_t)(Rbase + row) * 512 + c4 * 4];
        float4 x = *(const float4*)&emb[(size_t)toks[row] * 512 + c4 * 4];
        *(float2*)&Ws[0][row][c4 * 4]     = make_float2(w.x, w.y);
        *(float2*)&Ws[0][row][c4 * 4 + 2] = make_float2(w.z, w.w);
        *(float2*)&Xs[0][row][c4 * 4]     = make_float2(x.x, x.y);
        *(float2*)&Xs[0][row][c4 * 4 + 2] = make_float2(x.z, x.w);
    }
    __syncthreads();
    int rl = tid & 15, mg = tid >> 4;
    ull acc[4][4] = {};
    float4 wst[2], xst[2];
    for (int kt = 0; kt < 16; kt++) {
        int cur = kt & 1;
        if (kt < 15) {
            int k0 = (kt + 1) * 32;
            #pragma unroll
            for (int q = 0; q < 2; q++) {
                int i = tid + 256 * q;
                int row = i >> 3, c4 = i & 7;
                wst[q] = *(const float4*)&Wih[(size_t)(Rbase + row) * 512 + k0 + c4 * 4];
                xst[q] = *(const float4*)&emb[(size_t)toks[row] * 512 + k0 + c4 * 4];
            }
        }
        #pragma unroll
        for (int kp = 0; kp < 16; kp++) {
            ull wv[4], xv[4];
            #pragma unroll
            for (int i = 0; i < 4; i++) wv[i] = ld2(&Ws[cur][rl + 16 * i][kp * 2]);
            #pragma unroll
            for (int j = 0; j < 4; j++) xv[j] = ld2(&Xs[cur][mg * 4 + j][kp * 2]);
            #pragma unroll
            for (int i = 0; i < 4; i++)
                #pragma unroll
                for (int j = 0; j < 4; j++)
                    acc[i][j] = fma2(wv[i], xv[j], acc[i][j]);
        }
        if (kt < 15) {
            __syncthreads();
            int nb = cur ^ 1;
            #pragma unroll
            for (int q = 0; q < 2; q++) {
                int i = tid + 256 * q;
                int row = i >> 3, c4 = i & 7;
                *(float2*)&Ws[nb][row][c4 * 4]     = make_float2(wst[q].x, wst[q].y);
                *(float2*)&Ws[nb][row][c4 * 4 + 2] = make_float2(wst[q].z, wst[q].w);
                *(float2*)&Xs[nb][row][c4 * 4]     = make_float2(xst[q].x, xst[q].y);
                *(float2*)&Xs[nb][row][c4 * 4 + 2] = make_float2(xst[q].z, xst[q].w);
            }
            __syncthreads();
        }
    }
    #pragma unroll
    for (int j = 0; j < 4; j++) {
        int m = mbase + mg * 4 + j;
        if (m >= MM) continue;
        #pragma unroll
        for (int i = 0; i < 4; i++) {
            int R = Rbase + rl + 16 * i;
            g_gx[((size_t)m << 11) + R] = sum2(acc[i][j]) + bih[R] + bhh[R];
        }
    }
}

// --------- grid barrier: REDG arrival (single counter), read-only poll -------
__device__ __forceinline__ void gbar(unsigned target) {
    __syncthreads();
    if (threadIdx.x == 0) {
        asm volatile("red.release.gpu.global.add.u32 [%0], 1;"
                     :: "l"(&g_arrive) : "memory");
        unsigned v;
        do {
            asm volatile("ld.acquire.gpu.global.u32 %0, [%1];"
                         : "=r"(v) : "l"(&g_arrive) : "memory");
        } while (v < target);
    }
    __syncthreads();
}

// arrival + release only (no wait yet) — lets stores after it overlap the poll
__device__ __forceinline__ void gbar_arrive() {
    __syncthreads();
    if (threadIdx.x == 0) {
        asm volatile("red.release.gpu.global.add.u32 [%0], 1;"
                     :: "l"(&g_arrive) : "memory");
    }
}
__device__ __forceinline__ void gbar_wait(unsigned target) {
    if (threadIdx.x == 0) {
        unsigned v;
        do {
            asm volatile("ld.acquire.gpu.global.u32 %0, [%1];"
                         : "=r"(v) : "l"(&g_arrive) : "memory");
        } while (v < target);
    }
    __syncthreads();
}

// ---------------- persistent kernel: h0 + counts + LSTM recurrence -----------
// 128 blocks x 256 threads. Block j owns output columns d in {4j..4j+3}
// (16 gate rows R = g*512 + 4j + c). One global barrier per step.
__global__ void __launch_bounds__(256) lstm_persistent(
        const float* __restrict__ Whh, const float* __restrict__ enc,
        const void* pad, const void* ptrm) {
    __shared__ ulonglong2 Wq_s[16][128];   // 32 KB
    __shared__ float psum[8][16][32];      // 16 KB
    __shared__ float hex[4][32];
    __shared__ int red1[256], red2[256];
    int tid = threadIdx.x;
    int bid = blockIdx.x;
    int lane = tid & 31, w = tid >> 5;
    int j = bid;

    // ---- phase 0: h0 partial sums over enc + pointer counts ----
    {
        int b = bid >> 2, ns = bid & 3;
        int d0 = tid * 2;
        int base = b * NN + ns * 512;
        ull a0 = 0, a1 = 0, a2 = 0, a3 = 0;
        for (int n = 0; n < 512; n += 4) {
            int i0 = base + n;
            if (getmask(pad, i0))     a0 = add2(a0, ld2(&enc[(size_t)(i0) * DD + d0]));
            if (getmask(pad, i0 + 1)) a1 = add2(a1, ld2(&enc[(size_t)(i0 + 1) * DD + d0]));
            if (getmask(pad, i0 + 2)) a2 = add2(a2, ld2(&enc[(size_t)(i0 + 2) * DD + d0]));
            if (getmask(pad, i0 + 3)) a3 = add2(a3, ld2(&enc[(size_t)(i0 + 3) * DD + d0]));
        }
        *(ull*)&g_h0part[(ns * BB + b) * DD + d0] = add2(add2(a0, a1), add2(a2, a3));
        if (ns == 0) {
            int c1 = 0, c2 = 0;
            for (int n = tid; n < NN; n += 256) {
                c1 += getmask(pad, b * NN + n) ? 1 : 0;
                c2 += getmask(ptrm, b * NN + n) ? 1 : 0;
            }
            red1[tid] = c1; red2[tid] = c2; __syncthreads();
            for (int s = 128; s > 0; s >>= 1) {
                if (tid < s) { red1[tid] += red1[tid + s]; red2[tid] += red2[tid + s]; }
                __syncthreads();
            }
            if (tid == 0) { g_cntpad[b] = (float)red1[0]; g_cntptr[b] = (float)red2[0]; }
        }
    }
    gbar(128);

    // ---- load W_hh rows for this block's 16 gate rows (once) ----
    for (int idx = tid; idx < 16 * 128; idx += 256) {
        int r = idx >> 7, q = idx & 127;
        int g = r >> 2, c = r & 3;
        int R = g * 512 + 4 * j + c;
        Wq_s[r][q] = ((const ulonglong2*)(Whh + (size_t)R * 512))[q];
    }

    // ---- h0 finalize for owned columns ----
    float creg = 0.f;
    if (tid < 128) {
        int c = tid >> 5, b = tid & 31;
        int d = 4 * j + c;
        float ssum = 0.f;
        #pragma unroll
        for (int z = 0; z < 4; z++) ssum += g_h0part[(z * BB + b) * DD + d];
        float h0 = ssum / g_cntpad[b];
        creg = h0;
        hex[c][b] = h0;
    }
    __syncthreads();
    if (tid < 32) {
        ulonglong2 u;
        u.x = pack2(hex[0][tid], hex[1][tid]);
        u.y = pack2(hex[2][tid], hex[3][tid]);
        g_hq[0][j][tid] = u;
    }
    gbar(256);

    // ---- recurrence: ONE barrier per step ----
    for (int t = 0; t < NSTEP; t++) {
        const longlong2* hq = (const longlong2*)&g_hq[t & 1][0][0];

        // prefetch the whole k-slice for this warp (MLP=16)
        longlong2 hv[16];
        #pragma unroll
        for (int qq = 0; qq < 16; qq++)
            hv[qq] = __ldcg(&hq[(w * 16 + qq) * 32 + lane]);

        ull acc[16] = {};
        #pragma unroll
        for (int qq = 0; qq < 16; qq++) {
            int q = w * 16 + qq;
            ull hx = (ull)hv[qq].x, hy = (ull)hv[qq].y;
            #pragma unroll
            for (int r = 0; r < 16; r++) {
                ulonglong2 wv = Wq_s[r][q];
                acc[r] = fma2(hx, wv.x, acc[r]);
                acc[r] = fma2(hy, wv.y, acc[r]);
            }
        }
        #pragma unroll
        for (int r = 0; r < 16; r++) psum[w][r][lane] = sum2(acc[r]);
        __syncthreads();

        float hn = 0.f;
        if (tid < 128) {
            int c = tid >> 5, b = tid & 31;
            const float* gx = g_gx + ((size_t)(t * BB + b) << 11) + 4 * j + c;
            float gi = gx[0], gf = gx[512], gg = gx[1024], go = gx[1536];
            #pragma unroll
            for (int w2 = 0; w2 < 8; w2++) {
                gi += psum[w2][c][b];
                gf += psum[w2][4 + c][b];
                gg += psum[w2][8 + c][b];
                go += psum[w2][12 + c][b];
            }
            float cn = sigm(gf) * creg + sigm(gi) * tanhf(gg);
            hn = sigm(go) * tanhf(cn);
            creg = cn;
            hex[c][b] = hn;
        }
        __syncthreads();
        if (tid < 32) {
            ulonglong2 u;
            u.x = pack2(hex[0][tid], hex[1][tid]);
            u.y = pack2(hex[2][tid], hex[3][tid]);
            g_hq[(t + 1) & 1][j][tid] = u;
        }
        // arrive (publishes g_hq), then overlap g_Hall store with the poll
        gbar_arrive();
        if (tid < 128) {
            int c = tid >> 5, b = tid & 31;
            g_Hall[(size_t)(t * BB + b) * DD + 4 * j + c] = hn;
        }
        gbar_wait(256 + 128u * (t + 1));
    }
}

// ---------------- hw: HW[m][n] = Hall[m]·W_att[n] ----------------------------
__global__ void __launch_bounds__(256) hw_kernel(const float* __restrict__ Watt) {
    __shared__ float As[64][66];
    __shared__ float Ws[64][66];
    int tid = threadIdx.x;
    int mbase = blockIdx.x * 64;
    int nbase = blockIdx.y * 64;
    int tx = tid & 15;
    int ty = tid >> 4;
    ull acc[4][4] = {};
    for (int k0 = 0; k0 < 512; k0 += 32) {
        __syncthreads();
        #pragma unroll
        for (int i = 0; i < 8; i++) {
            int lin = tid + 256 * i;
            int row = lin >> 5, c = lin & 31;
            int m = mbase + row;
            As[row][c] = (m < MM) ? g_Hall[((size_t)m << 9) + k0 + c] : 0.f;
            Ws[row][c] = Watt[(size_t)(nbase + row) * 512 + k0 + c];
        }
        __syncthreads();
        #pragma unroll
        for (int kp = 0; kp < 16; kp++) {
            ull av[4], wv[4];
            #pragma unroll
            for (int jj = 0; jj < 4; jj++) av[jj] = ld2(&As[ty * 4 + jj][kp * 2]);
            #pragma unroll
            for (int i = 0; i < 4; i++) wv[i] = ld2(&Ws[tx + 16 * i][kp * 2]);
            #pragma unroll
            for (int i = 0; i < 4; i++)
                #pragma unroll
                for (int jj = 0; jj < 4; jj++)
                    acc[i][jj] = fma2(av[jj], wv[i], acc[i][jj]);
        }
    }
    #pragma unroll
    for (int jj = 0; jj < 4; jj++) {
        int m = mbase + ty * 4 + jj;
        if (m >= MM) continue;
        #pragma unroll
        for (int i = 0; i < 4; i++)
            g_HW[((size_t)m << 9) + nbase + tx + 16 * i] = sum2(acc[i][jj]);
    }
}

// ---------------- scores[t][b][n] = enc[b][n]·HW[t*B+b] ----------------------
__global__ void __launch_bounds__(256) scores_kernel(const float* __restrict__ enc) {
    __shared__ float Es[256][34];
    __shared__ float Hs[32][34];
    int tid = threadIdx.x;
    int nbase = blockIdx.x << 8;
    int b = blockIdx.y;
    int nl = tid & 31;
    int tg = tid >> 5;
    ull acc[8][4] = {};
    for (int k0 = 0; k0 < 512; k0 += 32) {
        __syncthreads();
        #pragma unroll
        for (int i = 0; i < 16; i++) {
            int lin = tid + 256 * i;
            int row = lin >> 4, c2 = lin & 15;
            *(ull*)&Es[row][c2 * 2] =
                ld2(&enc[((size_t)(b * NN + nbase + row) << 9) + k0 + c2 * 2]);
        }
        #pragma unroll
        for (int i = 0; i < 2; i++) {
            int lin = tid + 256 * i;
            int row = lin >> 4, c2 = lin & 15;
            *(ull*)&Hs[row][c2 * 2] = (row < NSTEP)
                ? ld2(&g_HW[((size_t)(row * BB + b) << 9) + k0 + c2 * 2]) : 0ull;
        }
        __syncthreads();
        #pragma unroll
        for (int kp = 0; kp < 16; kp++) {
            ull ev[8], hv[4];
            #pragma unroll
            for (int i = 0; i < 8; i++) ev[i] = ld2(&Es[nl + 32 * i][kp * 2]);
            #pragma unroll
            for (int jj = 0; jj < 4; jj++) hv[jj] = ld2(&Hs[tg * 4 + jj][kp * 2]);
            #pragma unroll
            for (int i = 0; i < 8; i++)
                #pragma unroll
                for (int jj = 0; jj < 4; jj++)
                    acc[i][jj] = fma2(ev[i], hv[jj], acc[i][jj]);
        }
    }
    #pragma unroll
    for (int jj = 0; jj < 4; jj++) {
        int t = tg * 4 + jj;
        if (t >= NSTEP) continue;
        #pragma unroll
        for (int i = 0; i < 8; i++)
            g_scores[((size_t)(t * BB + b) << 11) + nbase + nl + 32 * i] = sum2(acc[i][jj]);
    }
}

// ---------------- softmax + threshold + scatter + eos ------------------------
__global__ void softmax_scatter_kernel(const void* ptrmask,
                                       const int* __restrict__ token_ids,
                                       const int* __restrict__ eosp,
                                       float* __restrict__ out) {
    int t = blockIdx.x, b = blockIdx.y, tid = threadIdx.x;
    __shared__ float sp[NN];
    __shared__ float red[256];
    const float* sc = g_scores + ((size_t)(t * BB) + b) * NN;

    float m = -1e30f;
    for (int n = tid; n < NN; n += 256) {
        bool pm = getmask(ptrmask, b * NN + n);
        float s = pm ? sc[n] : -1e30f;
        sp[n] = s;
        m = fmaxf(m, s);
    }
    red[tid] = m; __syncthreads();
    for (int s = 128; s > 0; s >>= 1) {
        if (tid < s) red[tid] = fmaxf(red[tid], red[tid + s]);
        __syncthreads();
    }
    m = red[0]; __syncthreads();

    float lsum = 0.f;
    for (int n = tid; n < NN; n += 256) {
        float s = sp[n];
        float e = (s > -1e29f) ? expf(s - m) : 0.f;
        sp[n] = e;
        lsum += e;
    }
    red[tid] = lsum; __syncthreads();
    for (int s = 128; s > 0; s >>= 1) {
        if (tid < s) red[tid] += red[tid + s];
        __syncthreads();
    }
    float sum = red[0];
    float thr = 1.0f / g_cntptr[b];
    float* orow = out + ((size_t)(t + 1)) * BB * VV + (size_t)b * VV;
    __syncthreads();

    float ks = 0.f;
    for (int n = tid; n < NN; n += 256) {
        float e = sp[n];
        if (e > 0.f) {
            float p = e / sum;
            if (p >= thr) {
                atomicAdd(&orow[token_ids[b * NN + n]], p);
                ks += p;
            }
        }
    }
    red[tid] = ks; __syncthreads();
    for (int s = 128; s > 0; s >>= 1) {
        if (tid < s) red[tid] += red[tid + s];
        __syncthreads();
    }
    if (tid == 0) {
        __threadfence();
        orow[eosp[0]] = 1.0f - red[0];
    }
}

// ---------------- host launcher ----------------------------------------------
extern "C" void kernel_launch(void* const* d_in, const int* in_sizes, int n_in,
                              void* d_out, int out_size) {
    const float* enc    = (const float*)d_in[0];
    const float* emb    = (const float*)d_in[1];
    const float* W_ih   = (const float*)d_in[2];
    const float* W_hh   = (const float*)d_in[3];
    const float* b_ih   = (const float*)d_in[4];
    const float* b_hh   = (const float*)d_in[5];
    const float* W_att  = (const float*)d_in[6];
    const void*  pad    = d_in[7];
    const void*  ptr    = d_in[8];
    const int*   tokid  = (const int*)d_in[9];
    const int*   target = (const int*)d_in[10];
    const int*   sosp   = (const int*)d_in[11];
    const int*   eosp   = (const int*)d_in[12];
    float* out = (float*)d_out;

    detect_kernel<<<1, 32>>>((const int*)pad);

    int n4 = (TT * BB * VV) / 4;
    zero_kernel<<<4096, 256>>>((float4*)out, n4);
    sos_kernel<<<1, 32>>>(out, sosp);

    {
        dim3 g(32, 16);
        xgemm_kernel<<<g, 256>>>(emb, W_ih, b_ih, b_hh, target, sosp);
    }

    lstm_persistent<<<128, 256>>>(W_hh, enc, pad, ptr);

    {
        dim3 g(16, 8);
        hw_kernel<<<g, 256>>>(W_att);
    }
    {
        dim3 g(8, BB);
        scores_kernel<<<g, 256>>>(enc);
    }
    {
        dim3 g(NSTEP, BB);
        softmax_scatter_kernel<<<g, 256>>>(ptr, tokid, eosp, out);
    }
}

// round 10
// speedup vs baseline: 1.2128x; 1.0496x over previous
#include <cuda_runtime.h>
#include <cuda_bf16.h>
#include <cstdint>

#define BB 32
#define NN 2048
#define DD 512
#define EE 512
#define VV 32000
#define TT 32
#define NSTEP 31
#define MM (NSTEP * BB)   // 992

typedef unsigned long long ull;

// ---------------- scratch ----------------------------------------------------
__device__ float g_h[BB * DD];
__device__ float g_Hall[MM * DD];
__device__ float g_HW[MM * DD];
__device__ float g_scores[MM * NN];         // 8.1 MB
__device__ float g_gx[MM * 4 * DD];         // 8.1 MB  (x-side gates + biases)
__device__ float g_gp[8 * BB * 4 * DD];     // 2 MB    (h-side partials, 8 k-slices)
__device__ float g_h0part[4 * BB * DD];
__device__ float g_cntpad[BB];
__device__ float g_cntptr[BB];
__device__ int   g_mask_mode;
__device__ unsigned g_arrive;

// ---------------- helpers -----------------------------------------------------
__device__ __forceinline__ bool getmask(const void* p, int idx) {
    int m = g_mask_mode;
    if (m == 1) return ((const int*)p)[idx] != 0;
    if (m == 2) return ((const float*)p)[idx] != 0.0f;
    return ((const unsigned char*)p)[idx] != 0;
}
__device__ __forceinline__ float sigm(float x) { return 1.0f / (1.0f + expf(-x)); }

__device__ __forceinline__ ull ld2(const float* p) { return *(const ull*)p; }
__device__ __forceinline__ ull fma2(ull a, ull b, ull c) {
    ull d;
    asm("fma.rn.f32x2 %0, %1, %2, %3;" : "=l"(d) : "l"(a), "l"(b), "l"(c));
    return d;
}
__device__ __forceinline__ ull add2(ull a, ull b) {
    ull d;
    asm("add.rn.f32x2 %0, %1, %2;" : "=l"(d) : "l"(a), "l"(b));
    return d;
}
__device__ __forceinline__ float sum2(ull v) {
    return __uint_as_float((unsigned)v) + __uint_as_float((unsigned)(v >> 32));
}

// ---------------- setup kernels ----------------------------------------------
__global__ void detect_kernel(const int* pad_as_int) {
    if (threadIdx.x == 0) {
        int v = pad_as_int[0];
        g_mask_mode = (v == 1) ? 1 : ((v == 0x3F800000) ? 2 : 0);
        g_arrive = 0;
    }
}

__global__ void zero_kernel(float4* out, int n4) {
    int idx = blockIdx.x * blockDim.x + threadIdx.x;
    int stride = gridDim.x * blockDim.x;
    float4 z = {0.f, 0.f, 0.f, 0.f};
    for (int i = idx; i < n4; i += stride) out[i] = z;
}

__global__ void sos_kernel(float* out, const int* sosp) {
    int b = threadIdx.x;
    if (b < BB) out[(size_t)b * VV + sosp[0]] = 1.0f;
}

// ---------------- xgemm: gates_x[m][R] = emb[tok(m)]·W_ih[R] + b_ih + b_hh ---
__global__ void __launch_bounds__(256) xgemm_kernel(
        const float* __restrict__ emb, const float* __restrict__ Wih,
        const float* __restrict__ bih, const float* __restrict__ bhh,
        const int* __restrict__ target, const int* __restrict__ sosp) {
    __shared__ float Ws[2][64][34];
    __shared__ float Xs[2][64][34];
    __shared__ int toks[64];
    int tid = threadIdx.x;
    int Rbase = blockIdx.x * 64;
    int mbase = blockIdx.y * 64;
    if (tid < 64) {
        int m = mbase + tid;
        int t = m >> 5, b = m & 31;
        int tok = sosp[0];
        if (m < MM && t > 0) tok = target[t * BB + b];
        toks[tid] = tok;
    }
    __syncthreads();
    #pragma unroll
    for (int q = 0; q < 2; q++) {
        int i = tid + 256 * q;
        int row = i >> 3, c4 = i & 7;
        float4 w = *(const float4*)&Wih[(size_t)(Rbase + row) * 512 + c4 * 4];
        float4 x = *(const float4*)&emb[(size_t)toks[row] * 512 + c4 * 4];
        *(float2*)&Ws[0][row][c4 * 4]     = make_float2(w.x, w.y);
        *(float2*)&Ws[0][row][c4 * 4 + 2] = make_float2(w.z, w.w);
        *(float2*)&Xs[0][row][c4 * 4]     = make_float2(x.x, x.y);
        *(float2*)&Xs[0][row][c4 * 4 + 2] = make_float2(x.z, x.w);
    }
    __syncthreads();
    int rl = tid & 15, mg = tid >> 4;
    ull acc[4][4] = {};
    float4 wst[2], xst[2];
    for (int kt = 0; kt < 16; kt++) {
        int cur = kt & 1;
        if (kt < 15) {
            int k0 = (kt + 1) * 32;
            #pragma unroll
            for (int q = 0; q < 2; q++) {
                int i = tid + 256 * q;
                int row = i >> 3, c4 = i & 7;
                wst[q] = *(const float4*)&Wih[(size_t)(Rbase + row) * 512 + k0 + c4 * 4];
                xst[q] = *(const float4*)&emb[(size_t)toks[row] * 512 + k0 + c4 * 4];
            }
        }
        #pragma unroll
        for (int kp = 0; kp < 16; kp++) {
            ull wv[4], xv[4];
            #pragma unroll
            for (int i = 0; i < 4; i++) wv[i] = ld2(&Ws[cur][rl + 16 * i][kp * 2]);
            #pragma unroll
            for (int j = 0; j < 4; j++) xv[j] = ld2(&Xs[cur][mg * 4 + j][kp * 2]);
            #pragma unroll
            for (int i = 0; i < 4; i++)
                #pragma unroll
                for (int j = 0; j < 4; j++)
                    acc[i][j] = fma2(wv[i], xv[j], acc[i][j]);
        }
        if (kt < 15) {
            __syncthreads();
            int nb = cur ^ 1;
            #pragma unroll
            for (int q = 0; q < 2; q++) {
                int i = tid + 256 * q;
                int row = i >> 3, c4 = i & 7;
                *(float2*)&Ws[nb][row][c4 * 4]     = make_float2(wst[q].x, wst[q].y);
                *(float2*)&Ws[nb][row][c4 * 4 + 2] = make_float2(wst[q].z, wst[q].w);
                *(float2*)&Xs[nb][row][c4 * 4]     = make_float2(xst[q].x, xst[q].y);
                *(float2*)&Xs[nb][row][c4 * 4 + 2] = make_float2(xst[q].z, xst[q].w);
            }
            __syncthreads();
        }
    }
    #pragma unroll
    for (int j = 0; j < 4; j++) {
        int m = mbase + mg * 4 + j;
        if (m >= MM) continue;
        #pragma unroll
        for (int i = 0; i < 4; i++) {
            int R = Rbase + rl + 16 * i;
            g_gx[((size_t)m << 11) + R] = sum2(acc[i][j]) + bih[R] + bhh[R];
        }
    }
}

// --------- grid barrier: REDG arrival (single counter), read-only poll -------
__device__ __forceinline__ void gbar(unsigned target) {
    __syncthreads();
    if (threadIdx.x == 0) {
        asm volatile("red.release.gpu.global.add.u32 [%0], 1;"
                     :: "l"(&g_arrive) : "memory");
        unsigned v;
        do {
            asm volatile("ld.acquire.gpu.global.u32 %0, [%1];"
                         : "=r"(v) : "l"(&g_arrive) : "memory");
        } while (v < target);
    }
    __syncthreads();
}

// ---------------- persistent kernel: h0 + counts + LSTM recurrence -----------
// 128 blocks x 256 threads — R4 structure: block = (dt = bid>>3, s = bid&7);
// W_hh slice [128 rows][64 k] in smem; h slice staged; partials via g_gp.
// Two read-poll barriers per step; gx prefetched before the GEMM.
__global__ void __launch_bounds__(256) lstm_persistent(
        const float* __restrict__ Whh, const float* __restrict__ enc,
        const void* pad, const void* ptrm) {
    __shared__ float Wsm[128][66];   // 33 KB
    __shared__ float hs[32][66];     // 8.25 KB
    __shared__ int red1[256], red2[256];
    int tid = threadIdx.x;
    int bid = blockIdx.x;

    // ---- phase 0: h0 partial sums over enc + pointer counts ----
    {
        int b = bid >> 2, ns = bid & 3;
        int d0 = tid * 2;
        int base = b * NN + ns * 512;
        ull a0 = 0, a1 = 0, a2 = 0, a3 = 0;
        for (int n = 0; n < 512; n += 4) {
            int i0 = base + n;
            if (getmask(pad, i0))     a0 = add2(a0, ld2(&enc[(size_t)(i0) * DD + d0]));
            if (getmask(pad, i0 + 1)) a1 = add2(a1, ld2(&enc[(size_t)(i0 + 1) * DD + d0]));
            if (getmask(pad, i0 + 2)) a2 = add2(a2, ld2(&enc[(size_t)(i0 + 2) * DD + d0]));
            if (getmask(pad, i0 + 3)) a3 = add2(a3, ld2(&enc[(size_t)(i0 + 3) * DD + d0]));
        }
        *(ull*)&g_h0part[(ns * BB + b) * DD + d0] = add2(add2(a0, a1), add2(a2, a3));
        if (ns == 0) {
            int c1 = 0, c2 = 0;
            for (int n = tid; n < NN; n += 256) {
                c1 += getmask(pad, b * NN + n) ? 1 : 0;
                c2 += getmask(ptrm, b * NN + n) ? 1 : 0;
            }
            red1[tid] = c1; red2[tid] = c2; __syncthreads();
            for (int s = 128; s > 0; s >>= 1) {
                if (tid < s) { red1[tid] += red1[tid + s]; red2[tid] += red2[tid + s]; }
                __syncthreads();
            }
            if (tid == 0) { g_cntpad[b] = (float)red1[0]; g_cntptr[b] = (float)red2[0]; }
        }
    }
    gbar(128);

    // ---- recurrence setup ----
    int dt = bid >> 3, s = bid & 7;
    int k0 = s * 64;

    // W_hh slice into smem once: rows lr = g*32+dl -> R = g*512 + dt*32 + dl
    for (int i = tid; i < 128 * 64; i += 256) {
        int lr = i >> 6, kk = i & 63;
        int R = ((lr >> 5) << 9) + (dt << 5) + (lr & 31);
        Wsm[lr][kk] = Whh[(size_t)R * 512 + k0 + kk];
    }

    // pointwise ownership + h0 finalize
    float creg = 0.f;
    int pd = 0, pb = 0;
    if (tid < 128) {
        int idx = bid * 128 + tid;
        pd = idx & 511; pb = idx >> 9;
        float ssum = 0.f;
        #pragma unroll
        for (int z = 0; z < 4; z++) ssum += g_h0part[(z * BB + pb) * DD + pd];
        float h0 = ssum / g_cntpad[pb];
        creg = h0;
        g_h[pb * DD + pd] = h0;
    }
    gbar(256);

    int tx = tid & 31;   // lr = tx + 32*j
    int ty = tid >> 5;   // b = ty*4 + i
    unsigned cnt = 256;

    for (int t = 0; t < NSTEP; t++) {
        // prefetch this step's gx gate values (independent of h)
        float pgi = 0.f, pgf = 0.f, pgg = 0.f, pgo = 0.f;
        if (tid < 128) {
            const float* gx = g_gx + ((size_t)(t * BB + pb) << 11);
            pgi = __ldcg(&gx[pd]);
            pgf = __ldcg(&gx[512 + pd]);
            pgg = __ldcg(&gx[1024 + pd]);
            pgo = __ldcg(&gx[1536 + pd]);
        }

        // stage h slice [32 b][64 k] (L2-fresh): 2048 floats as 1024 x 8B
        #pragma unroll
        for (int q = 0; q < 4; q++) {
            int i = tid + q * 256;
            int b2 = i >> 5, jj = i & 31;
            long long v = __ldcg((const long long*)&g_h[b2 * DD + k0 + jj * 2]);
            *(ull*)&hs[b2][jj * 2] = (ull)v;
        }
        __syncthreads();

        ull acc[4][4] = {};
        #pragma unroll 8
        for (int kp = 0; kp < 32; kp++) {
            ull hv[4], wv[4];
            #pragma unroll
            for (int i = 0; i < 4; i++) hv[i] = ld2(&hs[ty * 4 + i][kp * 2]);
            #pragma unroll
            for (int j = 0; j < 4; j++) wv[j] = ld2(&Wsm[tx + 32 * j][kp * 2]);
            #pragma unroll
            for (int i = 0; i < 4; i++)
                #pragma unroll
                for (int j = 0; j < 4; j++)
                    acc[i][j] = fma2(hv[i], wv[j], acc[i][j]);
        }
        #pragma unroll
        for (int i = 0; i < 4; i++) {
            int b = ty * 4 + i;
            #pragma unroll
            for (int j = 0; j < 4; j++)
                g_gp[((s * BB + b) << 11) + (j << 9) + (dt << 5) + tx] = sum2(acc[i][j]);
        }

        cnt += 128; gbar(cnt);   // partials ready

        if (tid < 128) {
            float gi = pgi, gf = pgf, gg = pgg, go = pgo;
            #pragma unroll
            for (int ss = 0; ss < 8; ss++) {
                const float* gp = g_gp + ((size_t)(ss * BB + pb) << 11);
                gi += __ldcg(&gp[pd]);
                gf += __ldcg(&gp[512 + pd]);
                gg += __ldcg(&gp[1024 + pd]);
                go += __ldcg(&gp[1536 + pd]);
            }
            float cn = sigm(gf) * creg + sigm(gi) * tanhf(gg);
            float hn = sigm(go) * tanhf(cn);
            creg = cn;
            g_h[pb * DD + pd] = hn;
            g_Hall[((size_t)(t * BB + pb) << 9) + pd] = hn;
        }

        cnt += 128; gbar(cnt);   // h ready
    }
}

// ---------------- hw: HW[m][n] = Hall[m]·W_att[n] ----------------------------
__global__ void __launch_bounds__(256) hw_kernel(const float* __restrict__ Watt) {
    __shared__ float As[64][66];
    __shared__ float Ws[64][66];
    int tid = threadIdx.x;
    int mbase = blockIdx.x * 64;
    int nbase = blockIdx.y * 64;
    int tx = tid & 15;
    int ty = tid >> 4;
    ull acc[4][4] = {};
    for (int k0 = 0; k0 < 512; k0 += 32) {
        __syncthreads();
        #pragma unroll
        for (int i = 0; i < 8; i++) {
            int lin = tid + 256 * i;
            int row = lin >> 5, c = lin & 31;
            int m = mbase + row;
            As[row][c] = (m < MM) ? g_Hall[((size_t)m << 9) + k0 + c] : 0.f;
            Ws[row][c] = Watt[(size_t)(nbase + row) * 512 + k0 + c];
        }
        __syncthreads();
        #pragma unroll
        for (int kp = 0; kp < 16; kp++) {
            ull av[4], wv[4];
            #pragma unroll
            for (int jj = 0; jj < 4; jj++) av[jj] = ld2(&As[ty * 4 + jj][kp * 2]);
            #pragma unroll
            for (int i = 0; i < 4; i++) wv[i] = ld2(&Ws[tx + 16 * i][kp * 2]);
            #pragma unroll
            for (int i = 0; i < 4; i++)
                #pragma unroll
                for (int jj = 0; jj < 4; jj++)
                    acc[i][jj] = fma2(av[jj], wv[i], acc[i][jj]);
        }
    }
    #pragma unroll
    for (int jj = 0; jj < 4; jj++) {
        int m = mbase + ty * 4 + jj;
        if (m >= MM) continue;
        #pragma unroll
        for (int i = 0; i < 4; i++)
            g_HW[((size_t)m << 9) + nbase + tx + 16 * i] = sum2(acc[i][jj]);
    }
}

// ---------------- scores[t][b][n] = enc[b][n]·HW[t*B+b] ----------------------
__global__ void __launch_bounds__(256) scores_kernel(const float* __restrict__ enc) {
    __shared__ float Es[256][34];
    __shared__ float Hs[32][34];
    int tid = threadIdx.x;
    int nbase = blockIdx.x << 8;
    int b = blockIdx.y;
    int nl = tid & 31;
    int tg = tid >> 5;
    ull acc[8][4] = {};
    for (int k0 = 0; k0 < 512; k0 += 32) {
        __syncthreads();
        #pragma unroll
        for (int i = 0; i < 16; i++) {
            int lin = tid + 256 * i;
            int row = lin >> 4, c2 = lin & 15;
            *(ull*)&Es[row][c2 * 2] =
                ld2(&enc[((size_t)(b * NN + nbase + row) << 9) + k0 + c2 * 2]);
        }
        #pragma unroll
        for (int i = 0; i < 2; i++) {
            int lin = tid + 256 * i;
            int row = lin >> 4, c2 = lin & 15;
            *(ull*)&Hs[row][c2 * 2] = (row < NSTEP)
                ? ld2(&g_HW[((size_t)(row * BB + b) << 9) + k0 + c2 * 2]) : 0ull;
        }
        __syncthreads();
        #pragma unroll
        for (int kp = 0; kp < 16; kp++) {
            ull ev[8], hv[4];
            #pragma unroll
            for (int i = 0; i < 8; i++) ev[i] = ld2(&Es[nl + 32 * i][kp * 2]);
            #pragma unroll
            for (int jj = 0; jj < 4; jj++) hv[jj] = ld2(&Hs[tg * 4 + jj][kp * 2]);
            #pragma unroll
            for (int i = 0; i < 8; i++)
                #pragma unroll
                for (int jj = 0; jj < 4; jj++)
                    acc[i][jj] = fma2(ev[i], hv[jj], acc[i][jj]);
        }
    }
    #pragma unroll
    for (int jj = 0; jj < 4; jj++) {
        int t = tg * 4 + jj;
        if (t >= NSTEP) continue;
        #pragma unroll
        for (int i = 0; i < 8; i++)
            g_scores[((size_t)(t * BB + b) << 11) + nbase + nl + 32 * i] = sum2(acc[i][jj]);
    }
}

// ---------------- softmax + threshold + scatter + eos ------------------------
__global__ void softmax_scatter_kernel(const void* ptrmask,
                                       const int* __restrict__ token_ids,
                                       const int* __restrict__ eosp,
                                       float* __restrict__ out) {
    int t = blockIdx.x, b = blockIdx.y, tid = threadIdx.x;
    __shared__ float sp[NN];
    __shared__ float red[256];
    const float* sc = g_scores + ((size_t)(t * BB) + b) * NN;

    float m = -1e30f;
    for (int n = tid; n < NN; n += 256) {
        bool pm = getmask(ptrmask, b * NN + n);
        float s = pm ? sc[n] : -1e30f;
        sp[n] = s;
        m = fmaxf(m, s);
    }
    red[tid] = m; __syncthreads();
    for (int s = 128; s > 0; s >>= 1) {
        if (tid < s) red[tid] = fmaxf(red[tid], red[tid + s]);
        __syncthreads();
    }
    m = red[0]; __syncthreads();

    float lsum = 0.f;
    for (int n = tid; n < NN; n += 256) {
        float s = sp[n];
        float e = (s > -1e29f) ? expf(s - m) : 0.f;
        sp[n] = e;
        lsum += e;
    }
    red[tid] = lsum; __syncthreads();
    for (int s = 128; s > 0; s >>= 1) {
        if (tid < s) red[tid] += red[tid + s];
        __syncthreads();
    }
    float sum = red[0];
    float thr = 1.0f / g_cntptr[b];
    float* orow = out + ((size_t)(t + 1)) * BB * VV + (size_t)b * VV;
    __syncthreads();

    float ks = 0.f;
    for (int n = tid; n < NN; n += 256) {
        float e = sp[n];
        if (e > 0.f) {
            float p = e / sum;
            if (p >= thr) {
                atomicAdd(&orow[token_ids[b * NN + n]], p);
                ks += p;
            }
        }
    }
    red[tid] = ks; __syncthreads();
    for (int s = 128; s > 0; s >>= 1) {
        if (tid < s) red[tid] += red[tid + s];
        __syncthreads();
    }
    if (tid == 0) {
        __threadfence();
        orow[eosp[0]] = 1.0f - red[0];
    }
}

// ---------------- host launcher ----------------------------------------------
extern "C" void kernel_launch(void* const* d_in, const int* in_sizes, int n_in,
                              void* d_out, int out_size) {
    const float* enc    = (const float*)d_in[0];
    const float* emb    = (const float*)d_in[1];
    const float* W_ih   = (const float*)d_in[2];
    const float* W_hh   = (const float*)d_in[3];
    const float* b_ih   = (const float*)d_in[4];
    const float* b_hh   = (const float*)d_in[5];
    const float* W_att  = (const float*)d_in[6];
    const void*  pad    = d_in[7];
    const void*  ptr    = d_in[8];
    const int*   tokid  = (const int*)d_in[9];
    const int*   target = (const int*)d_in[10];
    const int*   sosp   = (const int*)d_in[11];
    const int*   eosp   = (const int*)d_in[12];
    float* out = (float*)d_out;

    detect_kernel<<<1, 32>>>((const int*)pad);

    int n4 = (TT * BB * VV) / 4;
    zero_kernel<<<4096, 256>>>((float4*)out, n4);
    sos_kernel<<<1, 32>>>(out, sosp);

    {
        dim3 g(32, 16);
        xgemm_kernel<<<g, 256>>>(emb, W_ih, b_ih, b_hh, target, sosp);
    }

    lstm_persistent<<<128, 256>>>(W_hh, enc, pad, ptr);

    {
        dim3 g(16, 8);
        hw_kernel<<<g, 256>>>(W_att);
    }
    {
        dim3 g(8, BB);
        scores_kernel<<<g, 256>>>(enc);
    }
    {
        dim3 g(NSTEP, BB);
        softmax_scatter_kernel<<<g, 256>>>(ptr, tokid, eosp, out);
    }
}